// round 7
// baseline (speedup 1.0000x reference)
#include <cuda_runtime.h>
#include <cuda_fp16.h>
#include <cuda_bf16.h>

#define NN 4096
#define FIN 128
#define FF 64
#define HH 8
#define MAXDEG 512
#define MT 512          // m-tile size in C2
#define NT 128          // n-tile size in C2
#define NPW 8           // nodes per warp in C2 (16 warps)
#define WCAP 96         // per-warp in-tile edge buffer capacity

#define LOG2E 1.44269504088896f

// scratch (allocation-free rule: device globals)
__device__ float   g_feats[HH * NN * FF];     // fp32 [h][n][f] (for scores)
__device__ __half2 g_feats_h2[HH * NN * 32];  // fp16 [h][n][fpair] (C2 tile source)
__device__ float   g_sself[HH * NN];          // pre-scaled by log2e
__device__ float   g_sneigh[HH * NN];         // pre-scaled by log2e
__device__ int     g_nbr[NN * MAXDEG];        // sorted neighbor lists
__device__ int     g_deg[NN];

__device__ __forceinline__ float ex2f(float x) {
    float r;
    asm("ex2.approx.ftz.f32 %0, %1;" : "=f"(r) : "f"(x));
    return r;
}

// ---------------------------------------------------------------------------
// Kernel A: feats[h] = X @ W[h]. 64x64 tile, 256 thr, 4x4/thread, K-chunk 32.
// grid (NN/64, HH) = (64, 8)
// ---------------------------------------------------------------------------
__global__ __launch_bounds__(256) void gemm_feats_kernel(
    const float* __restrict__ X, const float* __restrict__ W)
{
    __shared__ float Xs[32 * 68];   // [k][row], 64 rows + pad 4
    __shared__ float Ws[32 * 68];   // [k][f],   64 cols + pad 4

    const int h  = blockIdx.y;
    const int r0 = blockIdx.x * 64;
    const int tid = threadIdx.x;
    const int tx = tid & 15;        // f group: cols tx*4..+3
    const int ty = tid >> 4;        // row group: rows ty*4..+3

    float acc[4][4];
#pragma unroll
    for (int i = 0; i < 4; i++)
#pragma unroll
        for (int j = 0; j < 4; j++) acc[i][j] = 0.0f;

    for (int kc = 0; kc < FIN; kc += 32) {
        // X chunk [64 rows][32 k] transposed into Xs[k][row]
        for (int i = tid; i < 64 * 8; i += 256) {
            int r = i >> 3, kq = (i & 7) * 4;
            float4 v = *(const float4*)(X + (r0 + r) * FIN + kc + kq);
            Xs[(kq + 0) * 68 + r] = v.x;
            Xs[(kq + 1) * 68 + r] = v.y;
            Xs[(kq + 2) * 68 + r] = v.z;
            Xs[(kq + 3) * 68 + r] = v.w;
        }
        // W chunk [32 k][64 f]
        for (int i = tid; i < 32 * 16; i += 256) {
            int k = i >> 4, fq = (i & 15) * 4;
            float4 v = *(const float4*)(W + h * FIN * FF + (kc + k) * FF + fq);
            *(float4*)(Ws + k * 68 + fq) = v;
        }
        __syncthreads();

#pragma unroll
        for (int k = 0; k < 32; k++) {
            float4 a = *(const float4*)(Xs + k * 68 + ty * 4);
            float4 b = *(const float4*)(Ws + k * 68 + tx * 4);
            float av[4] = {a.x, a.y, a.z, a.w};
            float bv[4] = {b.x, b.y, b.z, b.w};
#pragma unroll
            for (int i = 0; i < 4; i++)
#pragma unroll
                for (int j = 0; j < 4; j++) acc[i][j] += av[i] * bv[j];
        }
        __syncthreads();
    }

#pragma unroll
    for (int i = 0; i < 4; i++) {
        int n = r0 + ty * 4 + i;
        int f = tx * 4;
        *(float4*)(g_feats + h * NN * FF + n * FF + f) =
            make_float4(acc[i][0], acc[i][1], acc[i][2], acc[i][3]);
        __half2 p0 = __floats2half2_rn(acc[i][0], acc[i][1]);
        __half2 p1 = __floats2half2_rn(acc[i][2], acc[i][3]);
        g_feats_h2[(h * NN + n) * 32 + (f >> 1)]     = p0;
        g_feats_h2[(h * NN + n) * 32 + (f >> 1) + 1] = p1;
    }
}

// ---------------------------------------------------------------------------
// Kernel B: scores, pre-scaled by log2e. one warp per (h,n). grid 4096.
// ---------------------------------------------------------------------------
__global__ __launch_bounds__(256) void score_kernel(
    const float* __restrict__ a_self, const float* __restrict__ a_neigh)
{
    const int warp = threadIdx.x >> 5;
    const int lane = threadIdx.x & 31;
    const int p = blockIdx.x * 8 + warp;       // p = h*NN + n
    const int h = p >> 12;

    float v0 = g_feats[p * FF + lane];
    float v1 = g_feats[p * FF + lane + 32];
    float ss = v0 * a_self[h * FF + lane]  + v1 * a_self[h * FF + lane + 32];
    float sn = v0 * a_neigh[h * FF + lane] + v1 * a_neigh[h * FF + lane + 32];
#pragma unroll
    for (int o = 16; o; o >>= 1) {
        ss += __shfl_xor_sync(0xffffffffu, ss, o);
        sn += __shfl_xor_sync(0xffffffffu, sn, o);
    }
    if (lane == 0) {
        g_sself[p]  = ss * LOG2E;
        g_sneigh[p] = sn * LOG2E;
    }
}

// ---------------------------------------------------------------------------
// Kernel C1: sorted neighbor compaction. one warp per node (order-preserving
// ballot compaction -> ascending m). grid 512, block 256 (8 warps).
// ---------------------------------------------------------------------------
__global__ __launch_bounds__(256) void compact_kernel(const int* __restrict__ A)
{
    const int warp = threadIdx.x >> 5;
    const int lane = threadIdx.x & 31;
    const int n = blockIdx.x * 8 + warp;
    const long long rb = (long long)n * NN;

    int base = 0;
    for (int i = 0; i < NN / 32; i++) {
        int a = A[rb + i * 32 + lane];
        unsigned mask = __ballot_sync(0xffffffffu, a != 0);
        if (a) {
            int pos = base + __popc(mask & ((1u << lane) - 1));
            if (pos < MAXDEG) g_nbr[n * MAXDEG + pos] = i * 32 + lane;
        }
        base += __popc(mask);
    }
    if (lane == 0) g_deg[n] = min(base, MAXDEG);
}

// ---------------------------------------------------------------------------
// Kernel C2: tiled sparse softmax + aggregation + ELU.
// grid (NN/NT, HH) = (32, 8), 512 threads (16 warps, 8 nodes each).
// m-tiles of 512: feats tile staged in smem; per-n probe of sorted nbr list
// computes exp2 weights (no max-sub needed: scores bounded), then 2-edge-packed
// LDS aggregation. exp(masked)==0 exactly, so only true neighbors appear.
// ---------------------------------------------------------------------------
__global__ __launch_bounds__(512) void attn_tiled_kernel(
    const float* __restrict__ bias, float* __restrict__ out)
{
    extern __shared__ char smem[];
    __half2* sF  = (__half2*)smem;                            // [MT][32]  64KB
    float*   sW  = (float*)(smem + MT * 32 * 4);              // [16][WCAP] 6KB
    short*   sMl = (short*)(smem + MT * 32 * 4 + 16 * WCAP * 4); // [16][WCAP] 3KB
    float*   sSS = (float*)(smem + MT * 32 * 4 + 16 * WCAP * 6); // [NT]

    const int h  = blockIdx.y;
    const int n0 = blockIdx.x * NT;
    const int tid  = threadIdx.x;
    const int warp = tid >> 5;
    const int lane = tid & 31;
    const int half = lane >> 4;      // 0/1: which edge of the pair
    const int fl   = lane & 15;      // f quad: f = fl*4..fl*4+3

    if (tid < NT) sSS[tid] = g_sself[h * NN + n0 + tid];

    // per-warp per-node state (register arrays, loops unrolled)
    int ptr[NPW], deg[NPW];
    float ssum[NPW];
    float acc[NPW][4];
#pragma unroll
    for (int nn = 0; nn < NPW; nn++) {
        int n = n0 + warp * NPW + nn;
        ptr[nn] = 0;
        deg[nn] = g_deg[n];
        ssum[nn] = 0.0f;
#pragma unroll
        for (int k = 0; k < 4; k++) acc[nn][k] = 0.0f;
    }

    const float* __restrict__ snb = g_sneigh + h * NN;
    float* sWw = sW  + warp * WCAP;
    short* sMw = sMl + warp * WCAP;

    for (int mt = 0; mt < NN / MT; mt++) {
        __syncthreads();
        // stage feats tile: thread tid copies row m = mt*MT + tid (128B)
        {
            const int4* src = (const int4*)(g_feats_h2 + (h * NN + mt * MT + tid) * 32);
            int4* dst = (int4*)(sF + tid * 32);
#pragma unroll
            for (int q = 0; q < 8; q++) dst[q] = src[q];
        }
        __syncthreads();

        const int mhi = (mt + 1) * MT;
        const int mbase = mt * MT;

#pragma unroll
        for (int nn = 0; nn < NPW; nn++) {
            const int nloc = warp * NPW + nn;
            const int n = n0 + nloc;
            const float ssv = sSS[nloc];

            // --- probe + weight phase ---
            int wcnt = 0;
            for (;;) {
                int idx = ptr[nn] + lane;
                int m = (idx < deg[nn]) ? g_nbr[n * MAXDEG + idx] : 0x7fffffff;
                bool in = (m < mhi);
                unsigned mask = __ballot_sync(0xffffffffu, in);
                int c = __popc(mask);
                float e = 0.0f;
                if (in) {
                    float sc = ssv + __ldg(snb + m);
                    sc = sc > 0.0f ? sc : 0.2f * sc;
                    e = ex2f(sc);
                    int pos = wcnt + lane;
                    if (pos < WCAP) {
                        sWw[pos] = e;
                        sMw[pos] = (short)(m - mbase);
                    }
                }
                float ec = e;
#pragma unroll
                for (int o = 16; o; o >>= 1) ec += __shfl_xor_sync(0xffffffffu, ec, o);
                ssum[nn] += ec;
                wcnt += c;
                ptr[nn] += c;
                if (c < 32) break;
            }
            if (wcnt > WCAP) wcnt = WCAP;
            __syncwarp();

            // --- aggregation phase: 2 edges per iteration ---
            for (int j = 0; j < wcnt; j += 2) {
                int jj = j + half;
                bool v = (jj < wcnt);
                float w   = v ? sWw[jj] : 0.0f;
                int mloc  = v ? (int)sMw[jj] : 0;
                // 2 consecutive half2 = 4 features for this lane's quad
                uint2 raw = *(const uint2*)(sF + mloc * 32 + fl * 2);
                __half2 h0 = *(__half2*)&raw.x;
                __half2 h1 = *(__half2*)&raw.y;
                float2 f0 = __half22float2(h0);
                float2 f1 = __half22float2(h1);
                acc[nn][0] += w * f0.x;
                acc[nn][1] += w * f0.y;
                acc[nn][2] += w * f1.x;
                acc[nn][3] += w * f1.y;
            }
            __syncwarp();
        }
    }

    // --- epilogue: merge half-warp partials, normalize, bias, ELU, store ---
#pragma unroll
    for (int nn = 0; nn < NPW; nn++) {
        const int n = n0 + warp * NPW + nn;
        float inv = 1.0f / ssum[nn];
        float4 o;
        float* po = &o.x;
#pragma unroll
        for (int k = 0; k < 4; k++) {
            float a = acc[nn][k] + __shfl_xor_sync(0xffffffffu, acc[nn][k], 16);
            float val = a * inv + bias[h * FF + fl * 4 + k];
            po[k] = val > 0.0f ? val : expm1f(val);
        }
        if (half == 0)
            *(float4*)(out + n * (HH * FF) + h * FF + fl * 4) = o;
    }
}

// ---------------------------------------------------------------------------
extern "C" void kernel_launch(void* const* d_in, const int* in_sizes, int n_in,
                              void* d_out, int out_size)
{
    const float* X       = (const float*)d_in[0];   // [4096,128]
    const int*   A       = (const int*)  d_in[1];   // [4096,4096]
    const float* W       = (const float*)d_in[2];   // [8,128,64]
    const float* b       = (const float*)d_in[3];   // [8,64]
    const float* a_self  = (const float*)d_in[4];   // [8,64]
    const float* a_neigh = (const float*)d_in[5];   // [8,64]
    float* out = (float*)d_out;                     // [4096, 512]

    const int smem_bytes = MT * 32 * 4 + 16 * WCAP * 6 + NT * 4 + 256;
    static bool attr_set = false;
    if (!attr_set) {
        cudaFuncSetAttribute(attn_tiled_kernel,
                             cudaFuncAttributeMaxDynamicSharedMemorySize, smem_bytes);
        attr_set = true;
    }

    gemm_feats_kernel<<<dim3(NN / 64, HH), 256>>>(X, W);
    score_kernel<<<NN, 256>>>(a_self, a_neigh);
    compact_kernel<<<NN / 8, 256>>>(A);
    attn_tiled_kernel<<<dim3(NN / NT, HH), 512, smem_bytes>>>(b, out);
}

// round 9
// speedup vs baseline: 1.1103x; 1.1103x over previous
#include <cuda_runtime.h>
#include <cuda_fp16.h>
#include <cuda_bf16.h>
#include <cstdint>

#define NN 4096
#define FIN 128
#define FF 64
#define HH 8
#define MAXDEG 512
#define LOG2E 1.44269504088896f

// scratch (allocation-free rule: device globals)
__device__ float  g_feats[HH * NN * FF];     // fp32 [h][n][f] (for scores)
__device__ __half g_featsB[HH * NN * FF];    // fp16 [h][n][f] (MMA B source)
__device__ float  g_sself[HH * NN];          // pre-scaled by log2e
__device__ float  g_sneigh[HH * NN];         // pre-scaled by log2e
__device__ int    g_nbr[NN * MAXDEG];        // sorted neighbor lists (CSR)
__device__ int    g_deg[NN];

__device__ __forceinline__ float ex2f(float x) {
    float r; asm("ex2.approx.ftz.f32 %0, %1;" : "=f"(r) : "f"(x)); return r;
}
__device__ __forceinline__ uint32_t smem_u32(const void* p) {
    uint32_t a;
    asm("{ .reg .u64 t; cvta.to.shared.u64 t, %1; cvt.u32.u64 %0, t; }" : "=r"(a) : "l"(p));
    return a;
}

// ---------------------------------------------------------------------------
// Kernel A: feats[h] = X @ W[h]. 64x64 tile, 256 thr, 4x4/thread, K-chunk 32.
// Epilogue writes fp32 [h][n][f] and fp16 [h][n][f].
// ---------------------------------------------------------------------------
__global__ __launch_bounds__(256) void gemm_feats_kernel(
    const float* __restrict__ X, const float* __restrict__ W)
{
    __shared__ float Xs[32 * 68];
    __shared__ float Ws[32 * 68];

    const int h  = blockIdx.y;
    const int r0 = blockIdx.x * 64;
    const int tid = threadIdx.x;
    const int tx = tid & 15;
    const int ty = tid >> 4;

    float acc[4][4];
#pragma unroll
    for (int i = 0; i < 4; i++)
#pragma unroll
        for (int j = 0; j < 4; j++) acc[i][j] = 0.0f;

    for (int kc = 0; kc < FIN; kc += 32) {
        for (int i = tid; i < 64 * 8; i += 256) {
            int r = i >> 3, kq = (i & 7) * 4;
            float4 v = *(const float4*)(X + (r0 + r) * FIN + kc + kq);
            Xs[(kq + 0) * 68 + r] = v.x;
            Xs[(kq + 1) * 68 + r] = v.y;
            Xs[(kq + 2) * 68 + r] = v.z;
            Xs[(kq + 3) * 68 + r] = v.w;
        }
        for (int i = tid; i < 32 * 16; i += 256) {
            int k = i >> 4, fq = (i & 15) * 4;
            float4 v = *(const float4*)(W + h * FIN * FF + (kc + k) * FF + fq);
            *(float4*)(Ws + k * 68 + fq) = v;
        }
        __syncthreads();
#pragma unroll
        for (int k = 0; k < 32; k++) {
            float4 a = *(const float4*)(Xs + k * 68 + ty * 4);
            float4 b = *(const float4*)(Ws + k * 68 + tx * 4);
            float av[4] = {a.x, a.y, a.z, a.w};
            float bv[4] = {b.x, b.y, b.z, b.w};
#pragma unroll
            for (int i = 0; i < 4; i++)
#pragma unroll
                for (int j = 0; j < 4; j++) acc[i][j] += av[i] * bv[j];
        }
        __syncthreads();
    }
#pragma unroll
    for (int i = 0; i < 4; i++) {
        int n = r0 + ty * 4 + i;
        *(float4*)(g_feats + (h * NN + n) * FF + tx * 4) =
            make_float4(acc[i][0], acc[i][1], acc[i][2], acc[i][3]);
        __half2 p0 = __floats2half2_rn(acc[i][0], acc[i][1]);
        __half2 p1 = __floats2half2_rn(acc[i][2], acc[i][3]);
        uint2 u = make_uint2(*(uint32_t*)&p0, *(uint32_t*)&p1);
        *(uint2*)(g_featsB + (h * NN + n) * FF + tx * 4) = u;
    }
}

// ---------------------------------------------------------------------------
// Kernel B: scores (pre-scaled by log2e). one warp per (h,n).
// ---------------------------------------------------------------------------
__global__ __launch_bounds__(256) void score_kernel(
    const float* __restrict__ a_self, const float* __restrict__ a_neigh)
{
    const int warp = threadIdx.x >> 5;
    const int lane = threadIdx.x & 31;
    const int p = blockIdx.x * 8 + warp;       // p = h*NN + n
    const int h = p >> 12;

    float v0 = g_feats[p * FF + lane];
    float v1 = g_feats[p * FF + lane + 32];
    float ss = v0 * a_self[h * FF + lane]  + v1 * a_self[h * FF + lane + 32];
    float sn = v0 * a_neigh[h * FF + lane] + v1 * a_neigh[h * FF + lane + 32];
#pragma unroll
    for (int o = 16; o; o >>= 1) {
        ss += __shfl_xor_sync(0xffffffffu, ss, o);
        sn += __shfl_xor_sync(0xffffffffu, sn, o);
    }
    if (lane == 0) { g_sself[p] = ss * LOG2E; g_sneigh[p] = sn * LOG2E; }
}

// ---------------------------------------------------------------------------
// Kernel C1: sorted neighbor compaction (ballot, order-preserving).
// ---------------------------------------------------------------------------
__global__ __launch_bounds__(256) void compact_kernel(const int* __restrict__ A)
{
    const int warp = threadIdx.x >> 5;
    const int lane = threadIdx.x & 31;
    const int n = blockIdx.x * 8 + warp;
    const long long rb = (long long)n * NN;

    int base = 0;
    for (int i = 0; i < NN / 32; i++) {
        int a = A[rb + i * 32 + lane];
        unsigned mask = __ballot_sync(0xffffffffu, a != 0);
        if (a) {
            int pos = base + __popc(mask & ((1u << lane) - 1));
            if (pos < MAXDEG) g_nbr[n * MAXDEG + pos] = i * 32 + lane;
        }
        base += __popc(mask);
    }
    if (lane == 0) g_deg[n] = min(base, MAXDEG);
}

// ---------------------------------------------------------------------------
// Kernel C2: warp-MMA attention aggregation (fp16 HMMA, fp32 accumulate).
// grid (NN/128, HH) = (32, 8), 256 threads (8 warps; warp w owns rows w*16..+15).
// Per m-tile (128): zero P [128n][136m] fp16, scatter exp2 weights from CSR,
// stage F [128m][72f] fp16, then mma.sync.m16n8k16 accumulating D[16,64]/warp
// in registers across all 32 tiles. Epilogue: normalize, bias, ELU, store.
// ---------------------------------------------------------------------------
#define PS 136                       // P row stride (halfs)
#define FS 72                        // F row stride (halfs)
#define SM_P 2048
#define SM_F (2048 + 128 * PS * 2)   // 2048 + 34816 = 36864
#define SM_TOTAL (36864 + 128 * FS * 2 + 64)

__global__ __launch_bounds__(256) void attn_mma_kernel(
    const float* __restrict__ bias, float* __restrict__ out)
{
    extern __shared__ char smem[];
    int*   sPtr = (int*)(smem);
    int*   sDeg = (int*)(smem + 512);
    float* sSS  = (float*)(smem + 1024);
    float* sSum = (float*)(smem + 1536);
    const uint32_t sb    = smem_u32(smem);
    const uint32_t pBase = sb + SM_P;
    const uint32_t fBase = sb + SM_F;

    const int tid  = threadIdx.x;
    const int wid  = tid >> 5;
    const int lane = tid & 31;
    const int h  = blockIdx.y;
    const int n0 = blockIdx.x * 128;
    const int r0 = wid * 16;

    if (tid < 128) {
        sPtr[tid] = 0;
        sSum[tid] = 0.0f;
        sDeg[tid] = g_deg[n0 + tid];
        sSS[tid]  = g_sself[h * NN + n0 + tid];
    }

    float d[8][4];
#pragma unroll
    for (int j = 0; j < 8; j++)
#pragma unroll
        for (int k = 0; k < 4; k++) d[j][k] = 0.0f;

    const float* __restrict__ snb = g_sneigh + h * NN;
    // ldmatrix source addresses (fixed per thread, offset per k-step/n-frag)
    const uint32_t aAddr0 = pBase + (uint32_t)(((r0 + (lane & 15)) * PS + ((lane >> 4) << 3)) * 2);
    const uint32_t bAddr0 = fBase + (uint32_t)((((lane & 7) + ((lane >> 3) & 1) * 8) * FS + ((lane >> 4) << 3)) * 2);

    for (int mt = 0; mt < 32; mt++) {
        __syncthreads();   // previous MMA done before overwriting P/F

        // --- zero P (128 rows x 128 cols) ---
        {
            int4 z = make_int4(0, 0, 0, 0);
#pragma unroll
            for (int it = 0; it < 8; it++) {
                int i = tid + it * 256;            // [0,2048)
                int row = i >> 4, q = i & 15;
                *(int4*)(smem + SM_P + row * (PS * 2) + q * 16) = z;
            }
        }
        // --- stage F tile [128m][64f] fp16 from g_featsB ---
        {
            const int mb = mt * 128;
#pragma unroll
            for (int it = 0; it < 4; it++) {
                int i = tid + it * 256;            // [0,1024)
                int m = i >> 3, q = i & 7;
                int4 v = *(const int4*)(g_featsB + (h * NN + mb + m) * FF + q * 8);
                *(int4*)(smem + SM_F + m * (FS * 2) + q * 16) = v;
            }
        }
        __syncthreads();

        // --- probe CSR + scatter exp2 weights into P (warp owns 16 rows) ---
        {
            const int mhi = mt * 128 + 128, mbase = mt * 128;
            for (int rr = 0; rr < 16; rr++) {
                int row = r0 + rr;
                int n = n0 + row;
                int ptrv = sPtr[row];
                int degv = sDeg[row];
                float ssv = sSS[row];
                float esum = 0.0f;
                int c;
                do {
                    int idx = ptrv + lane;
                    int m = (idx < degv) ? g_nbr[n * MAXDEG + idx] : 0x7fffffff;
                    bool in = (m < mhi);
                    unsigned msk = __ballot_sync(0xffffffffu, in);
                    c = __popc(msk);
                    if (in) {
                        float sc = ssv + __ldg(snb + m);
                        sc = sc > 0.0f ? sc : 0.2f * sc;
                        float e = ex2f(sc);
                        esum += e;
                        ((__half*)(smem + SM_P))[row * PS + (m - mbase)] = __float2half(e);
                    }
                    ptrv += c;
                } while (c == 32);
#pragma unroll
                for (int o = 16; o; o >>= 1) esum += __shfl_xor_sync(0xffffffffu, esum, o);
                if (lane == 0) { sPtr[row] = ptrv; sSum[row] += esum; }
            }
        }
        __syncthreads();

        // --- MMA: D[16,64] += P[16,128] @ F[128,64] ---
#pragma unroll
        for (int ks = 0; ks < 8; ks++) {
            uint32_t a0, a1, a2, a3;
            asm volatile("ldmatrix.sync.aligned.m8n8.x4.shared.b16 {%0,%1,%2,%3}, [%4];"
                : "=r"(a0), "=r"(a1), "=r"(a2), "=r"(a3)
                : "r"(aAddr0 + ks * 32));
#pragma unroll
            for (int nf = 0; nf < 4; nf++) {
                uint32_t b0, b1, b2, b3;
                asm volatile("ldmatrix.sync.aligned.m8n8.x4.trans.shared.b16 {%0,%1,%2,%3}, [%4];"
                    : "=r"(b0), "=r"(b1), "=r"(b2), "=r"(b3)
                    : "r"(bAddr0 + (uint32_t)(ks * 16 * (FS * 2) + nf * 32)));
                asm volatile(
                    "mma.sync.aligned.m16n8k16.row.col.f32.f16.f16.f32 "
                    "{%0,%1,%2,%3}, {%4,%5,%6,%7}, {%8,%9}, {%0,%1,%2,%3};"
                    : "+f"(d[nf*2][0]), "+f"(d[nf*2][1]), "+f"(d[nf*2][2]), "+f"(d[nf*2][3])
                    : "r"(a0), "r"(a1), "r"(a2), "r"(a3), "r"(b0), "r"(b1));
                asm volatile(
                    "mma.sync.aligned.m16n8k16.row.col.f32.f16.f16.f32 "
                    "{%0,%1,%2,%3}, {%4,%5,%6,%7}, {%8,%9}, {%0,%1,%2,%3};"
                    : "+f"(d[nf*2+1][0]), "+f"(d[nf*2+1][1]), "+f"(d[nf*2+1][2]), "+f"(d[nf*2+1][3])
                    : "r"(a0), "r"(a1), "r"(a2), "r"(a3), "r"(b2), "r"(b3));
            }
        }
    }
    __syncthreads();

    // --- epilogue: normalize, bias, ELU, store ---
    {
        const int g  = lane >> 2;            // row group 0..7
        const int cq = (lane & 3) * 2;       // col pair base
        const int rowA = r0 + g;
        const int rowB = r0 + g + 8;
        const float invA = 1.0f / sSum[rowA];
        const float invB = 1.0f / sSum[rowB];
        const int nA = n0 + rowA;
        const int nB = n0 + rowB;
#pragma unroll
        for (int j = 0; j < 8; j++) {
            int c = j * 8 + cq;
            float bs0 = __ldg(bias + h * FF + c);
            float bs1 = __ldg(bias + h * FF + c + 1);
            float vA0 = d[j][0] * invA + bs0;
            float vA1 = d[j][1] * invA + bs1;
            float vB0 = d[j][2] * invB + bs0;
            float vB1 = d[j][3] * invB + bs1;
            vA0 = vA0 > 0.0f ? vA0 : expm1f(vA0);
            vA1 = vA1 > 0.0f ? vA1 : expm1f(vA1);
            vB0 = vB0 > 0.0f ? vB0 : expm1f(vB0);
            vB1 = vB1 > 0.0f ? vB1 : expm1f(vB1);
            *(float2*)(out + nA * (HH * FF) + h * FF + c) = make_float2(vA0, vA1);
            *(float2*)(out + nB * (HH * FF) + h * FF + c) = make_float2(vB0, vB1);
        }
    }
}

// ---------------------------------------------------------------------------
extern "C" void kernel_launch(void* const* d_in, const int* in_sizes, int n_in,
                              void* d_out, int out_size)
{
    const float* X       = (const float*)d_in[0];   // [4096,128]
    const int*   A       = (const int*)  d_in[1];   // [4096,4096]
    const float* W       = (const float*)d_in[2];   // [8,128,64]
    const float* b       = (const float*)d_in[3];   // [8,64]
    const float* a_self  = (const float*)d_in[4];   // [8,64]
    const float* a_neigh = (const float*)d_in[5];   // [8,64]
    float* out = (float*)d_out;                     // [4096, 512]

    static bool attr_set = false;
    if (!attr_set) {
        cudaFuncSetAttribute(attn_mma_kernel,
                             cudaFuncAttributeMaxDynamicSharedMemorySize, SM_TOTAL);
        attr_set = true;
    }

    gemm_feats_kernel<<<dim3(NN / 64, HH), 256>>>(X, W);
    score_kernel<<<NN, 256>>>(a_self, a_neigh);
    compact_kernel<<<NN / 8, 256>>>(A);
    attn_mma_kernel<<<dim3(NN / 128, HH), 256, SM_TOTAL>>>(b, out);
}

// round 12
// speedup vs baseline: 2.1906x; 1.9730x over previous
#include <cuda_runtime.h>
#include <cuda_fp16.h>
#include <cuda_bf16.h>
#include <cstdint>

#define NN 4096
#define FIN 128
#define FF 64
#define HH 8
#define MAXDEG 512
#define LOG2E 1.44269504088896f

// scratch (allocation-free rule: device globals)
__device__ float  g_feats[HH * NN * FF];     // fp32 [h][n][f] (for scores)
__device__ __half g_featsB[HH * NN * FF];    // fp16 [h][n][f] (MMA B source)
__device__ float  g_sself[HH * NN];          // pre-scaled by log2e
__device__ float  g_sneigh[HH * NN];         // pre-scaled by log2e
__device__ int    g_nbr[NN * MAXDEG];        // sorted neighbor lists (CSR)
__device__ int    g_tcnt[NN * 32];           // edges per (node, 128-m-tile)

__device__ __forceinline__ float ex2f(float x) {
    float r; asm("ex2.approx.ftz.f32 %0, %1;" : "=f"(r) : "f"(x)); return r;
}
__device__ __forceinline__ uint32_t smem_u32(const void* p) {
    uint32_t a;
    asm("{ .reg .u64 t; cvta.to.shared.u64 t, %1; cvt.u32.u64 %0, t; }" : "=r"(a) : "l"(p));
    return a;
}
__device__ __forceinline__ void cp16(uint32_t dst, const void* src) {
    asm volatile("cp.async.cg.shared.global [%0], [%1], 16;" :: "r"(dst), "l"(src));
}

// ---------------------------------------------------------------------------
// Kernel A: feats[h] = X @ W[h]. 64x64 tile, 256 thr, 4x4/thread, K-chunk 32.
// Epilogue writes fp32 and fp16 copies.
// ---------------------------------------------------------------------------
__global__ __launch_bounds__(256) void gemm_feats_kernel(
    const float* __restrict__ X, const float* __restrict__ W)
{
    __shared__ float Xs[32 * 68];
    __shared__ float Ws[32 * 68];

    const int h  = blockIdx.y;
    const int r0 = blockIdx.x * 64;
    const int tid = threadIdx.x;
    const int tx = tid & 15;
    const int ty = tid >> 4;

    float acc[4][4];
#pragma unroll
    for (int i = 0; i < 4; i++)
#pragma unroll
        for (int j = 0; j < 4; j++) acc[i][j] = 0.0f;

    for (int kc = 0; kc < FIN; kc += 32) {
        for (int i = tid; i < 64 * 8; i += 256) {
            int r = i >> 3, kq = (i & 7) * 4;
            float4 v = *(const float4*)(X + (r0 + r) * FIN + kc + kq);
            Xs[(kq + 0) * 68 + r] = v.x;
            Xs[(kq + 1) * 68 + r] = v.y;
            Xs[(kq + 2) * 68 + r] = v.z;
            Xs[(kq + 3) * 68 + r] = v.w;
        }
        for (int i = tid; i < 32 * 16; i += 256) {
            int k = i >> 4, fq = (i & 15) * 4;
            float4 v = *(const float4*)(W + h * FIN * FF + (kc + k) * FF + fq);
            *(float4*)(Ws + k * 68 + fq) = v;
        }
        __syncthreads();
#pragma unroll
        for (int k = 0; k < 32; k++) {
            float4 a = *(const float4*)(Xs + k * 68 + ty * 4);
            float4 b = *(const float4*)(Ws + k * 68 + tx * 4);
            float av[4] = {a.x, a.y, a.z, a.w};
            float bv[4] = {b.x, b.y, b.z, b.w};
#pragma unroll
            for (int i = 0; i < 4; i++)
#pragma unroll
                for (int j = 0; j < 4; j++) acc[i][j] += av[i] * bv[j];
        }
        __syncthreads();
    }
#pragma unroll
    for (int i = 0; i < 4; i++) {
        int n = r0 + ty * 4 + i;
        *(float4*)(g_feats + (h * NN + n) * FF + tx * 4) =
            make_float4(acc[i][0], acc[i][1], acc[i][2], acc[i][3]);
        __half2 p0 = __floats2half2_rn(acc[i][0], acc[i][1]);
        __half2 p1 = __floats2half2_rn(acc[i][2], acc[i][3]);
        uint2 u = make_uint2(*(uint32_t*)&p0, *(uint32_t*)&p1);
        *(uint2*)(g_featsB + (h * NN + n) * FF + tx * 4) = u;
    }
}

// ---------------------------------------------------------------------------
// Kernel B: scores (pre-scaled by log2e). one warp per (h,n).
// ---------------------------------------------------------------------------
__global__ __launch_bounds__(256) void score_kernel(
    const float* __restrict__ a_self, const float* __restrict__ a_neigh)
{
    const int warp = threadIdx.x >> 5;
    const int lane = threadIdx.x & 31;
    const int p = blockIdx.x * 8 + warp;       // p = h*NN + n
    const int h = p >> 12;

    float v0 = g_feats[p * FF + lane];
    float v1 = g_feats[p * FF + lane + 32];
    float ss = v0 * a_self[h * FF + lane]  + v1 * a_self[h * FF + lane + 32];
    float sn = v0 * a_neigh[h * FF + lane] + v1 * a_neigh[h * FF + lane + 32];
#pragma unroll
    for (int o = 16; o; o >>= 1) {
        ss += __shfl_xor_sync(0xffffffffu, ss, o);
        sn += __shfl_xor_sync(0xffffffffu, sn, o);
    }
    if (lane == 0) { g_sself[p] = ss * LOG2E; g_sneigh[p] = sn * LOG2E; }
}

// ---------------------------------------------------------------------------
// Kernel C1: sorted neighbor compaction (ballot, order-preserving) + per-tile
// edge counts (128-node m-tiles => 4 chunks of 32 per tile).
// ---------------------------------------------------------------------------
__global__ __launch_bounds__(256) void compact_kernel(const int* __restrict__ A)
{
    const int warp = threadIdx.x >> 5;
    const int lane = threadIdx.x & 31;
    const int n = blockIdx.x * 8 + warp;
    const long long rb = (long long)n * NN;

    int base = 0, tcnt = 0;
    for (int i = 0; i < NN / 32; i++) {
        int a = A[rb + i * 32 + lane];
        unsigned mask = __ballot_sync(0xffffffffu, a != 0);
        int c = __popc(mask);
        if (a) {
            int pos = base + __popc(mask & ((1u << lane) - 1));
            if (pos < MAXDEG) g_nbr[n * MAXDEG + pos] = i * 32 + lane;
        }
        base += c;
        tcnt += c;
        if ((i & 3) == 3) {
            if (lane == 0) g_tcnt[n * 32 + (i >> 2)] = tcnt;
            tcnt = 0;
        }
    }
}

// ---------------------------------------------------------------------------
// Kernel C2: warp-MMA attention aggregation (fp16 HMMA, fp32 accumulate).
// grid (NN/64, HH) = (64, 8), 256 threads.
// n-tile 64, m-tiles of 128. Per tile: zero P [64n][136m], stage sneigh tile
// (512B smem), edge-parallel probe (4 thr/row) scatters exp2 weights into P,
// cp.async double-buffered F [128m][72f], then mma.m16n8k16: warps (w,w+4)
// share rows (w&3)*16..+15, cols (w>>2)*32..+31. Accumulate in regs, 32 tiles.
// ---------------------------------------------------------------------------
#define PS 136                       // P row stride (halfs); 272B = 17*16
#define FS 72                        // F row stride (halfs); 144B = 9*16
#define SM_PTR 0                     // int[64]
#define SM_SS  256                   // float[64]
#define SM_SUM 512                   // float[64]
#define SM_SNB 768                   // float[128]
#define SM_P   2048                  // 64*272 = 17408
#define SM_F0  19456                 // 128*144 = 18432
#define SM_F1  37888
#define SM_TOTAL 56320

__global__ __launch_bounds__(256) void attn_mma_kernel(
    const float* __restrict__ bias, float* __restrict__ out)
{
    extern __shared__ char smem[];
    int*   sPtr = (int*)(smem + SM_PTR);
    float* sSS  = (float*)(smem + SM_SS);
    float* sSum = (float*)(smem + SM_SUM);
    float* sSnb = (float*)(smem + SM_SNB);
    __half* sP  = (__half*)(smem + SM_P);
    const uint32_t sb = smem_u32(smem);

    const int tid  = threadIdx.x;
    const int wid  = tid >> 5;
    const int lane = tid & 31;
    const int h  = blockIdx.y;
    const int n0 = blockIdx.x * 64;

    const int r0 = (wid & 3) * 16;       // MMA row block
    const int cb = (wid >> 2) * 32;      // MMA col half

    const int prow = tid >> 2;           // probe: row 0..63
    const int psl  = tid & 3;            // probe: slot 0..3
    const int pn   = n0 + prow;

    if (tid < 64) {
        sPtr[tid] = 0;
        sSum[tid] = 0.0f;
        sSS[tid]  = g_sself[h * NN + n0 + tid];
    }

    float d[4][4];
#pragma unroll
    for (int j = 0; j < 4; j++)
#pragma unroll
        for (int k = 0; k < 4; k++) d[j][k] = 0.0f;

    const float* __restrict__ snb = g_sneigh + h * NN;

    // ldmatrix base addresses
    const uint32_t aAddr0 = sb + SM_P +
        (uint32_t)(((r0 + (lane & 15)) * PS + ((lane >> 4) << 3)) * 2);
    const uint32_t bCol = (uint32_t)((((lane & 7) + ((lane >> 3) & 1) * 8) * FS +
                                     ((lane >> 4) << 3) + cb) * 2);

    // prologue: stage F tile 0 into F0
    {
#pragma unroll
        for (int it = 0; it < 4; it++) {
            int i = tid + it * 256;
            int m = i >> 3, q = i & 7;
            cp16(sb + SM_F0 + (uint32_t)(m * (FS * 2) + q * 16),
                 g_featsB + (h * NN + m) * FF + q * 8);
        }
        asm volatile("cp.async.commit_group;" ::: "memory");
    }

    for (int mt = 0; mt < 32; mt++) {
        const int mb = mt * 128;
        const int buf = mt & 1;

        __syncthreads();   // previous MMA done: P, sSnb free

        // --- zero own P row segment (4 thr x 64B = 256B/row, cols 0..127) ---
        {
            int4 z = make_int4(0, 0, 0, 0);
#pragma unroll
            for (int q = 0; q < 4; q++)
                *(int4*)(smem + SM_P + prow * (PS * 2) + (psl * 4 + q) * 16) = z;
        }
        // --- stage sneigh tile (128 floats) ---
        if (tid < 128) sSnb[tid] = snb[mb + tid];
        __syncthreads();

        // --- edge-parallel probe + scatter (4 threads per row) ---
        {
            int ptrv = sPtr[prow];
            int cnt  = g_tcnt[pn * 32 + mt];
            float ssv = sSS[prow];
            const int* nbp = g_nbr + pn * MAXDEG + ptrv;
            float esum = 0.0f;

            // fast path: up to 12 edges per row (3 slots x 4 threads)
            int ms[3]; bool pv[3];
#pragma unroll
            for (int t = 0; t < 3; t++) {
                int j = psl + t * 4;
                pv[t] = (j < cnt);
                ms[t] = pv[t] ? nbp[j] : mb;
            }
#pragma unroll
            for (int t = 0; t < 3; t++) {
                if (pv[t]) {
                    float sc = ssv + sSnb[ms[t] - mb];
                    sc = sc > 0.0f ? sc : 0.2f * sc;
                    float e = ex2f(sc);
                    esum += e;
                    sP[prow * PS + (ms[t] - mb)] = __float2half(e);
                }
            }
            // rare overflow path
            for (int j = 12 + psl; j < cnt; j += 4) {
                int m = nbp[j];
                float sc = ssv + sSnb[m - mb];
                sc = sc > 0.0f ? sc : 0.2f * sc;
                float e = ex2f(sc);
                esum += e;
                sP[prow * PS + (m - mb)] = __float2half(e);
            }
            esum += __shfl_xor_sync(0xffffffffu, esum, 1);
            esum += __shfl_xor_sync(0xffffffffu, esum, 2);
            if (psl == 0) {
                sSum[prow] += esum;
                sPtr[prow] = ptrv + cnt;
            }
        }

        // --- stage next F tile into other buffer (overlaps with MMA) ---
        if (mt < 31) {
            uint32_t fb = sb + (buf ? SM_F0 : SM_F1);
            const int mbn = (mt + 1) * 128;
#pragma unroll
            for (int it = 0; it < 4; it++) {
                int i = tid + it * 256;
                int m = i >> 3, q = i & 7;
                cp16(fb + (uint32_t)(m * (FS * 2) + q * 16),
                     g_featsB + (h * NN + mbn + m) * FF + q * 8);
            }
            asm volatile("cp.async.commit_group;" ::: "memory");
            asm volatile("cp.async.wait_group 1;" ::: "memory");
        } else {
            asm volatile("cp.async.wait_group 0;" ::: "memory");
        }
        __syncthreads();   // P scattered + F[buf] arrived, visible to all

        // --- MMA: D[16,32] += P[16,128] @ F[128,32] ---
        const uint32_t bAddr0 = sb + (buf ? SM_F1 : SM_F0) + bCol;
#pragma unroll
        for (int ks = 0; ks < 8; ks++) {
            uint32_t a0, a1, a2, a3;
            asm volatile("ldmatrix.sync.aligned.m8n8.x4.shared.b16 {%0,%1,%2,%3}, [%4];"
                : "=r"(a0), "=r"(a1), "=r"(a2), "=r"(a3)
                : "r"(aAddr0 + ks * 32));
#pragma unroll
            for (int nf = 0; nf < 2; nf++) {
                uint32_t b0, b1, b2, b3;
                asm volatile("ldmatrix.sync.aligned.m8n8.x4.trans.shared.b16 {%0,%1,%2,%3}, [%4];"
                    : "=r"(b0), "=r"(b1), "=r"(b2), "=r"(b3)
                    : "r"(bAddr0 + (uint32_t)(ks * 16 * (FS * 2) + nf * 32)));
                asm volatile(
                    "mma.sync.aligned.m16n8k16.row.col.f32.f16.f16.f32 "
                    "{%0,%1,%2,%3}, {%4,%5,%6,%7}, {%8,%9}, {%0,%1,%2,%3};"
                    : "+f"(d[nf*2][0]), "+f"(d[nf*2][1]), "+f"(d[nf*2][2]), "+f"(d[nf*2][3])
                    : "r"(a0), "r"(a1), "r"(a2), "r"(a3), "r"(b0), "r"(b1));
                asm volatile(
                    "mma.sync.aligned.m16n8k16.row.col.f32.f16.f16.f32 "
                    "{%0,%1,%2,%3}, {%4,%5,%6,%7}, {%8,%9}, {%0,%1,%2,%3};"
                    : "+f"(d[nf*2+1][0]), "+f"(d[nf*2+1][1]), "+f"(d[nf*2+1][2]), "+f"(d[nf*2+1][3])
                    : "r"(a0), "r"(a1), "r"(a2), "r"(a3), "r"(b2), "r"(b3));
            }
        }
    }
    __syncthreads();

    // --- epilogue: normalize, bias, ELU, store ---
    {
        const int g  = lane >> 2;            // row group 0..7
        const int cq = (lane & 3) * 2;       // col pair base
        const int rowA = r0 + g;
        const int rowB = r0 + g + 8;
        const float invA = 1.0f / sSum[rowA];
        const float invB = 1.0f / sSum[rowB];
        const int nA = n0 + rowA;
        const int nB = n0 + rowB;
#pragma unroll
        for (int j = 0; j < 4; j++) {
            int c = cb + j * 8 + cq;
            float bs0 = __ldg(bias + h * FF + c);
            float bs1 = __ldg(bias + h * FF + c + 1);
            float vA0 = d[j][0] * invA + bs0;
            float vA1 = d[j][1] * invA + bs1;
            float vB0 = d[j][2] * invB + bs0;
            float vB1 = d[j][3] * invB + bs1;
            vA0 = vA0 > 0.0f ? vA0 : expm1f(vA0);
            vA1 = vA1 > 0.0f ? vA1 : expm1f(vA1);
            vB0 = vB0 > 0.0f ? vB0 : expm1f(vB0);
            vB1 = vB1 > 0.0f ? vB1 : expm1f(vB1);
            *(float2*)(out + nA * (HH * FF) + h * FF + c) = make_float2(vA0, vA1);
            *(float2*)(out + nB * (HH * FF) + h * FF + c) = make_float2(vB0, vB1);
        }
    }
}

// ---------------------------------------------------------------------------
extern "C" void kernel_launch(void* const* d_in, const int* in_sizes, int n_in,
                              void* d_out, int out_size)
{
    const float* X       = (const float*)d_in[0];   // [4096,128]
    const int*   A       = (const int*)  d_in[1];   // [4096,4096]
    const float* W       = (const float*)d_in[2];   // [8,128,64]
    const float* b       = (const float*)d_in[3];   // [8,64]
    const float* a_self  = (const float*)d_in[4];   // [8,64]
    const float* a_neigh = (const float*)d_in[5];   // [8,64]
    float* out = (float*)d_out;                     // [4096, 512]

    static bool attr_set = false;
    if (!attr_set) {
        cudaFuncSetAttribute(attn_mma_kernel,
                             cudaFuncAttributeMaxDynamicSharedMemorySize, SM_TOTAL);
        attr_set = true;
    }

    gemm_feats_kernel<<<dim3(NN / 64, HH), 256>>>(X, W);
    score_kernel<<<NN, 256>>>(a_self, a_neigh);
    compact_kernel<<<NN / 8, 256>>>(A);
    attn_mma_kernel<<<dim3(NN / 64, HH), 256, SM_TOTAL>>>(b, out);
}